// round 1
// baseline (speedup 1.0000x reference)
#include <cuda_runtime.h>

#define N 8192
#define NMASK (N - 1)
#define LOG2N 13
#define THREADS 256
#define BLOCKS 4096

__global__ void bt_zero_out(float* out) { *out = 0.0f; }

__device__ __forceinline__ float softplus_stable(float d) {
    // log(1 + exp(d)) = max(d,0) + log(1 + exp(-|d|)), stable for all d
    float t = fabsf(d);
    return fmaxf(d, 0.0f) + __logf(1.0f + __expf(-t));
}

__global__ void __launch_bounds__(THREADS)
bt_loss_kernel(const float* __restrict__ win,
               const float* __restrict__ betas,
               float* __restrict__ out) {
    const int total4 = (N * N) / 4;  // 16M float4 elements
    const int stride = gridDim.x * blockDim.x;

    float acc = 0.0f;

    for (int p = blockIdx.x * blockDim.x + threadIdx.x; p < total4; p += stride) {
        int e = p << 2;            // linear element index of first of 4
        int i = e >> LOG2N;        // row
        int j = e & NMASK;         // col of first element (aligned to 4)

        float bi = __ldg(betas + i);
        float4 bj = __ldg(reinterpret_cast<const float4*>(betas) + (j >> 2));
        float4 w  = __ldg(reinterpret_cast<const float4*>(win) + p);

        float d0 = bj.x - bi;
        float d1 = bj.y - bi;
        float d2 = bj.z - bi;
        float d3 = bj.w - bi;

        float s0 = softplus_stable(d0);
        float s1 = softplus_stable(d1);
        float s2 = softplus_stable(d2);
        float s3 = softplus_stable(d3);

        // mask diagonal (i == j+k)
        acc += (j + 0 != i) ? w.x * s0 : 0.0f;
        acc += (j + 1 != i) ? w.y * s1 : 0.0f;
        acc += (j + 2 != i) ? w.z * s2 : 0.0f;
        acc += (j + 3 != i) ? w.w * s3 : 0.0f;
    }

    // warp reduction
    #pragma unroll
    for (int off = 16; off > 0; off >>= 1)
        acc += __shfl_xor_sync(0xFFFFFFFFu, acc, off);

    __shared__ float warp_sums[THREADS / 32];
    int lane = threadIdx.x & 31;
    int wid  = threadIdx.x >> 5;
    if (lane == 0) warp_sums[wid] = acc;
    __syncthreads();

    if (wid == 0) {
        float v = (lane < THREADS / 32) ? warp_sums[lane] : 0.0f;
        #pragma unroll
        for (int off = 4; off > 0; off >>= 1)
            v += __shfl_xor_sync(0xFFFFFFFFu, v, off);
        if (lane == 0)
            atomicAdd(out, v);
    }
}

extern "C" void kernel_launch(void* const* d_in, const int* in_sizes, int n_in,
                              void* d_out, int out_size) {
    const float* win   = (const float*)d_in[0];
    const float* betas = (const float*)d_in[1];
    float* out = (float*)d_out;

    bt_zero_out<<<1, 1>>>(out);
    bt_loss_kernel<<<BLOCKS, THREADS>>>(win, betas, out);
}

// round 2
// speedup vs baseline: 1.0786x; 1.0786x over previous
#include <cuda_runtime.h>

#define N 8192
#define THREADS 256
#define F4_PER_ROW (N / 4)            // 2048 float4 per row
#define ITERS (F4_PER_ROW / THREADS)  // 8 float4 per thread
#define LOG2E 1.44269504088896340736f
#define LN2   0.69314718055994530942f

__global__ void bt_zero_out(float* out) { *out = 0.0f; }

// softplus in log2 units: log2(1 + 2^x) = max(x,0) + log2(1 + 2^(-|x|))
__device__ __forceinline__ float softplus2(float x) {
    float e = exp2f(0.0f - fabsf(x));        // MUFU.EX2 with -|x| operand modifier
    return fmaxf(x, 0.0f) + __log2f(1.0f + e);
}

__global__ void __launch_bounds__(THREADS)
bt_row_kernel(const float* __restrict__ win,
              const float* __restrict__ betas,
              float* __restrict__ out) {
    const int row = blockIdx.x;
    const float bi   = __ldg(betas + row);
    const float nbiL = -bi * LOG2E;           // block-uniform

    const float4* wrow = reinterpret_cast<const float4*>(win) + (size_t)row * F4_PER_ROW;
    const float4* b4   = reinterpret_cast<const float4*>(betas);

    float acc0 = 0.0f, acc1 = 0.0f;

    #pragma unroll
    for (int k = 0; k < ITERS; k++) {
        const int p = k * THREADS + threadIdx.x;
        float4 w  = __ldg(wrow + p);
        float4 bj = __ldg(b4 + p);

        float x0 = fmaf(bj.x, LOG2E, nbiL);
        float x1 = fmaf(bj.y, LOG2E, nbiL);
        float x2 = fmaf(bj.z, LOG2E, nbiL);
        float x3 = fmaf(bj.w, LOG2E, nbiL);

        acc0 = fmaf(w.x, softplus2(x0), acc0);
        acc1 = fmaf(w.y, softplus2(x1), acc1);
        acc0 = fmaf(w.z, softplus2(x2), acc0);
        acc1 = fmaf(w.w, softplus2(x3), acc1);
    }

    float acc = acc0 + acc1;

    // Remove the diagonal term (j == row), recomputed with identical FP ops so
    // the cancellation is exact up to reduction-order rounding.
    if (threadIdx.x == 0) {
        float wd = __ldg(win + (size_t)row * N + row);
        float xd = fmaf(bi, LOG2E, nbiL);
        acc -= wd * softplus2(xd);
    }

    // warp reduction
    #pragma unroll
    for (int off = 16; off > 0; off >>= 1)
        acc += __shfl_xor_sync(0xFFFFFFFFu, acc, off);

    __shared__ float warp_sums[THREADS / 32];
    const int lane = threadIdx.x & 31;
    const int wid  = threadIdx.x >> 5;
    if (lane == 0) warp_sums[wid] = acc;
    __syncthreads();

    if (wid == 0) {
        float v = (lane < THREADS / 32) ? warp_sums[lane] : 0.0f;
        #pragma unroll
        for (int off = 4; off > 0; off >>= 1)
            v += __shfl_xor_sync(0xFFFFFFFFu, v, off);
        if (lane == 0)
            atomicAdd(out, v * LN2);   // convert log2 units -> natural log once
    }
}

extern "C" void kernel_launch(void* const* d_in, const int* in_sizes, int n_in,
                              void* d_out, int out_size) {
    const float* win   = (const float*)d_in[0];
    const float* betas = (const float*)d_in[1];
    float* out = (float*)d_out;

    bt_zero_out<<<1, 1>>>(out);
    bt_row_kernel<<<N, THREADS>>>(win, betas, out);
}